// round 6
// baseline (speedup 1.0000x reference)
#include <cuda_runtime.h>
#include <cstdint>

// ---------------------------------------------------------------------------
// Sparse (occupancy-masked) 3D U-Net, 96^3, NF=16.
// R5: co-mapped warp-per-tap gather conv: lane = output channel, uniform
// broadcast x reads, register weights, scalar conflict-free acc RMW,
// per-warp acc copies (tap-partitioned => deterministic), 64-voxel tiles.
// ---------------------------------------------------------------------------

#define G0 96
#define G1 48
#define G2 24
#define NV0 (G0*G0*G0)   // 884736
#define NV1 (G1*G1*G1)   // 110592
#define NV2 (G2*G2*G2)   // 13824
#define CB0 (NV0/256)
#define CB1 (NV1/256)
#define CB2 (NV2/256)
#define NB0 ((NV0+127)/128)
#define NB1 ((NV1+127)/128)
#define NB2 ((NV2+127)/128)
#define NVT0 (NV0/64)    // 13824  64-voxel tiles
#define NVT1 (NV1/64)    // 1728
#define NVT2 (NV2/64)    // 216
#define ENTCAP64 1728    // 64*27 entries per tile

// Activations, channel-major [voxel][channel]
__device__ float g_XM  [NV0];
__device__ float g_CAT0[(size_t)32*NV0];
__device__ float g_A32 [(size_t)32*NV0];
__device__ float g_A16a[(size_t)16*NV0];
__device__ float g_A16b[(size_t)16*NV0];
__device__ float g_B32a[(size_t)32*NV1];
__device__ float g_B32b[(size_t)32*NV1];
__device__ float g_CAT1[(size_t)64*NV1];
__device__ float g_B64 [(size_t)64*NV1];
__device__ float g_C64a[(size_t)64*NV2];
__device__ float g_C64b[(size_t)64*NV2];
__device__ float g_C64c[(size_t)64*NV2];
__device__ float g_M1[NV1];
__device__ float g_M2[NV2];
__device__ float g_WT[64*64*27];           // transposed weights [tap][ci][co]

__device__ int g_LIST0[NV0], g_LIST1[NV1], g_LIST2[NV2];
__device__ int g_NA0[NV0];
__device__ int g_TAP0[(size_t)27*NV0];
__device__ int g_ENT0[(size_t)NVT0*ENTCAP64];
__device__ int g_ENT1[(size_t)NVT1*ENTCAP64];
__device__ int g_ENT2[(size_t)NVT2*ENTCAP64];
__device__ int g_SEG0[NVT0*28], g_SEG1[NVT1*28], g_SEG2[NVT2*28];
__device__ int g_SGW0[NVT0*27], g_SGW1[NVT1*27], g_SGW2[NVT2*27];
__device__ int g_SEGC[NVT0*27];
__device__ int g_CNT[4];
__device__ int g_BCNT[CB0], g_BOFF[CB0];

// ---------------------------------------------------------------------------
__global__ void k_mask_input(const float* __restrict__ x,
                             const float* __restrict__ occ,
                             float* __restrict__ xm, int n)
{
    int v = blockIdx.x * blockDim.x + threadIdx.x;
    if (v < n) xm[v] = x[v] * occ[v];
}

__global__ void k_maxpool(const float* __restrict__ in,
                          float* __restrict__ out, int gout)
{
    int v = blockIdx.x * blockDim.x + threadIdx.x;
    int n = gout * gout * gout;
    if (v >= n) return;
    int gin = gout * 2;
    int z = v / (gout * gout), y = (v / gout) % gout, x = v % gout;
    float mx = 0.f;
    #pragma unroll
    for (int a = 0; a < 2; a++)
        #pragma unroll
        for (int b = 0; b < 2; b++)
            #pragma unroll
            for (int c = 0; c < 2; c++)
                mx = fmaxf(mx, in[((size_t)(2*z+a)*gin + (2*y+b))*gin + (2*x+c)]);
    out[v] = mx;
}

// --- deterministic compaction ---------------------------------------------
__global__ void k_count(const float* __restrict__ m, int n, int* __restrict__ bcnt)
{
    int v = blockIdx.x * 256 + threadIdx.x;
    bool a = (v < n) && (m[v] != 0.f);
    unsigned bal = __ballot_sync(0xffffffffu, a);
    __shared__ int wc[8];
    if ((threadIdx.x & 31) == 0) wc[threadIdx.x >> 5] = __popc(bal);
    __syncthreads();
    if (threadIdx.x == 0) {
        int s = 0;
        #pragma unroll
        for (int i = 0; i < 8; i++) s += wc[i];
        bcnt[blockIdx.x] = s;
    }
}

__global__ void k_scan(const int* __restrict__ bcnt, int nb,
                       int* __restrict__ boff, int* __restrict__ total)
{
    __shared__ int sh[1024];
    __shared__ int carry;
    if (threadIdx.x == 0) carry = 0;
    __syncthreads();
    for (int base = 0; base < nb; base += 1024) {
        int i = base + threadIdx.x;
        int v = (i < nb) ? bcnt[i] : 0;
        sh[threadIdx.x] = v;
        __syncthreads();
        for (int d = 1; d < 1024; d <<= 1) {
            int t = (threadIdx.x >= d) ? sh[threadIdx.x - d] : 0;
            __syncthreads();
            sh[threadIdx.x] += t;
            __syncthreads();
        }
        if (i < nb) boff[i] = carry + sh[threadIdx.x] - v;
        __syncthreads();
        if (threadIdx.x == 0) carry += sh[1023];
        __syncthreads();
    }
    if (threadIdx.x == 0) *total = carry;
}

__global__ void k_emit(const float* __restrict__ m, int n,
                       const int* __restrict__ boff, int* __restrict__ list)
{
    int v = blockIdx.x * 256 + threadIdx.x;
    bool a = (v < n) && (m[v] != 0.f);
    unsigned bal = __ballot_sync(0xffffffffu, a);
    __shared__ int wc[8];
    if ((threadIdx.x & 31) == 0) wc[threadIdx.x >> 5] = __popc(bal);
    __syncthreads();
    int wid = threadIdx.x >> 5;
    int off = boff[blockIdx.x];
    for (int i = 0; i < wid; i++) off += wc[i];
    off += __popc(bal & ((1u << (threadIdx.x & 31)) - 1u));
    if (a) list[off] = v;
}

// --- per-voxel tap lists (for CIN==1 conv_in and planar out_b) ------------
__global__ void k_taps(const float* __restrict__ m, const int* __restrict__ list,
                       const int* __restrict__ cntp, int g, int cap,
                       int* __restrict__ TAP, int* __restrict__ NA)
{
    int cnt = *cntp;
    int t = blockIdx.x * 128 + threadIdx.x;
    if (t >= cnt) return;
    int v = list[t];
    int gg = g * g;
    int z = v / gg, y = (v / g) % g, x = v % g;
    int na = 0;
    #pragma unroll
    for (int dz = -1; dz <= 1; dz++) {
        int zz = z + dz; if ((unsigned)zz >= (unsigned)g) continue;
        #pragma unroll
        for (int dy = -1; dy <= 1; dy++) {
            int yy = y + dy; if ((unsigned)yy >= (unsigned)g) continue;
            int ro = (zz * g + yy) * g;
            #pragma unroll
            for (int dx = -1; dx <= 1; dx++) {
                int xx = x + dx; if ((unsigned)xx >= (unsigned)g) continue;
                int o = ro + xx;
                if (__ldg(m + o) != 0.f) {
                    int tap = (dz + 1) * 9 + (dy + 1) * 3 + (dx + 1);
                    TAP[(size_t)na * cap + t] = (tap << 24) | o;
                    na++;
                }
            }
        }
    }
    NA[t] = na;
}

// --- per-(64-voxel tile, tap) entry lists ---------------------------------
__global__ void k_zeron(int* __restrict__ a, int n)
{
    int i = blockIdx.x * 256 + threadIdx.x;
    if (i < n) a[i] = 0;
}

__global__ void k_entcnt(const float* __restrict__ m, const int* __restrict__ list,
                         const int* __restrict__ cntp, int g, int* __restrict__ segc)
{
    int cnt = *cntp;
    int t = blockIdx.x * 128 + threadIdx.x;
    if (t >= cnt) return;
    int v = list[t];
    int b = t >> 6;
    int gg = g * g;
    int z = v / gg, y = (v / g) % g, x = v % g;
    #pragma unroll
    for (int dz = -1; dz <= 1; dz++) {
        int zz = z + dz; if ((unsigned)zz >= (unsigned)g) continue;
        #pragma unroll
        for (int dy = -1; dy <= 1; dy++) {
            int yy = y + dy; if ((unsigned)yy >= (unsigned)g) continue;
            int ro = (zz * g + yy) * g;
            #pragma unroll
            for (int dx = -1; dx <= 1; dx++) {
                int xx = x + dx; if ((unsigned)xx >= (unsigned)g) continue;
                if (__ldg(m + ro + xx) != 0.f) {
                    int tap = (dz + 1) * 9 + (dy + 1) * 3 + (dx + 1);
                    atomicAdd(&segc[b * 27 + tap], 1);
                }
            }
        }
    }
}

__global__ void k_segscan(const int* __restrict__ segc, int nb,
                          int* __restrict__ seg, int* __restrict__ segw)
{
    int b = blockIdx.x * 256 + threadIdx.x;
    if (b >= nb) return;
    int s = 0;
    #pragma unroll
    for (int t = 0; t < 27; t++) {
        seg[b * 28 + t] = s;
        segw[b * 27 + t] = s;
        s += segc[b * 27 + t];
    }
    seg[b * 28 + 27] = s;
}

// entry = (vin << 11) | (slot << 5) | tap   (vin < 2^20, slot < 64, tap < 27)
__global__ void k_entscatter(const float* __restrict__ m, const int* __restrict__ list,
                             const int* __restrict__ cntp, int g,
                             int* __restrict__ segw, int* __restrict__ ENT)
{
    int cnt = *cntp;
    int t = blockIdx.x * 128 + threadIdx.x;
    if (t >= cnt) return;
    int v = list[t];
    int b = t >> 6;
    int slot = t & 63;
    int gg = g * g;
    int z = v / gg, y = (v / g) % g, x = v % g;
    #pragma unroll
    for (int dz = -1; dz <= 1; dz++) {
        int zz = z + dz; if ((unsigned)zz >= (unsigned)g) continue;
        #pragma unroll
        for (int dy = -1; dy <= 1; dy++) {
            int yy = y + dy; if ((unsigned)yy >= (unsigned)g) continue;
            int ro = (zz * g + yy) * g;
            #pragma unroll
            for (int dx = -1; dx <= 1; dx++) {
                int xx = x + dx; if ((unsigned)xx >= (unsigned)g) continue;
                int o = ro + xx;
                if (__ldg(m + o) != 0.f) {
                    int tap = (dz + 1) * 9 + (dy + 1) * 3 + (dx + 1);
                    int pos = atomicAdd(&segw[b * 27 + tap], 1);
                    ENT[(size_t)b * ENTCAP64 + pos] = (o << 11) | (slot << 5) | tap;
                }
            }
        }
    }
}

// --- weight transpose: OIDHW -> [tap][ci][co] ------------------------------
__global__ void k_wtrans(const float* __restrict__ w, int cin, int cout,
                         float* __restrict__ wt)
{
    int i = blockIdx.x * 256 + threadIdx.x;
    int tot = cout * cin * 27;
    if (i >= tot) return;
    int co = i % cout;
    int r = i / cout;
    int ci = r % cin;
    int tap = r / cin;
    wt[i] = w[((size_t)co * cin + ci) * 27 + tap];
}

// ---------------------------------------------------------------------------
// Co-mapped warp-per-tap gather conv. Warp w owns taps {w, w+4, ...}. All 32
// lanes process the same entry: lane = output channel. x row read via uniform
// broadcast __ldg(float4); weights per-lane in registers (reload per tap);
// scalar acc RMW into per-warp smem copy (conflict-free); deterministic
// (fixed tap partition, ascending taps, fixed final 4-way reduce).
// ---------------------------------------------------------------------------
template<int CIN, int COB, bool RELU>
__launch_bounds__(128)
__global__ void convg2(const float* __restrict__ in, int istr,
                       const float* __restrict__ wt, int couttot,
                       const int* __restrict__ ENT, const int* __restrict__ SEG,
                       const int* __restrict__ list, const int* __restrict__ cntp,
                       float* __restrict__ out, int ostr)
{
    constexpr int NSL  = 64;
    constexpr int ASTR = COB + 1;
    __shared__ float acc[4 * NSL * ASTR];
    const int cnt = *cntp;
    const int b = blockIdx.x;
    if (b * NSL >= cnt) return;
    const int co0  = blockIdx.y * COB;
    const int tid  = threadIdx.x;
    const int wid  = tid >> 5;
    const int lane = tid & 31;

    for (int i = tid; i < 4 * NSL * ASTR; i += 128) acc[i] = 0.f;
    __syncthreads();

    float w[CIN];
    float* accw = &acc[wid * NSL * ASTR];

    for (int tap = wid; tap < 27; tap += 4) {
        const int s = SEG[b * 28 + tap];
        const int e = SEG[b * 28 + tap + 1];
        if (s == e) continue;
        if (lane < COB) {
            #pragma unroll
            for (int ci = 0; ci < CIN; ci++)
                w[ci] = __ldg(wt + (size_t)(tap * CIN + ci) * couttot + co0 + lane);
        }
        for (int i = s; i < e; i++) {
            const int ent  = __ldg(ENT + (size_t)b * ENTCAP64 + i);
            const int slot = (ent >> 5) & 63;
            const int vin  = ((unsigned)ent) >> 11;
            const float* xr = in + (size_t)vin * istr;
            float sacc = 0.f;
            #pragma unroll
            for (int c4 = 0; c4 < CIN / 4; c4++) {
                float4 xq = __ldg(reinterpret_cast<const float4*>(xr + c4 * 4));
                sacc += xq.x * w[c4*4+0];
                sacc += xq.y * w[c4*4+1];
                sacc += xq.z * w[c4*4+2];
                sacc += xq.w * w[c4*4+3];
            }
            if (lane < COB)
                accw[slot * ASTR + lane] += sacc;
        }
    }
    __syncthreads();

    const int t0 = b * NSL;
    for (int i = tid; i < NSL * COB; i += 128) {
        const int slot = i / COB, co = i - slot * COB;
        const int t = t0 + slot;
        if (t < cnt) {
            float r = acc[(0 * NSL + slot) * ASTR + co]
                    + acc[(1 * NSL + slot) * ASTR + co]
                    + acc[(2 * NSL + slot) * ASTR + co]
                    + acc[(3 * NSL + slot) * ASTR + co];
            if (RELU) r = fmaxf(r, 0.f);
            out[(size_t)list[t] * ostr + co0 + co] = r;
        }
    }
}

// ---------------------------------------------------------------------------
// R3-style conv kept for CIN==1 (conv_in) and planar-out (out_b) layers.
// ---------------------------------------------------------------------------
template<int CIN, int COB, bool RELU, int CHUNK, bool OUTP>
__launch_bounds__(128)
__global__ void conv3cm(const float* __restrict__ in, int istr,
                        const float* __restrict__ wgl,
                        const int* __restrict__ TAP, const int* __restrict__ NAs,
                        const int* __restrict__ list, const int* __restrict__ cntp,
                        float* __restrict__ out, int ostr, int cap)
{
    constexpr int WPAD = COB + 1;
    __shared__ float wsh[CHUNK * 27 * WPAD];
    const int cnt = *cntp;
    if (blockIdx.x * 128 >= cnt) return;
    const int co0 = blockIdx.y * COB;
    const int t   = blockIdx.x * 128 + threadIdx.x;
    const bool act = t < cnt;
    const int v  = act ? list[t] : 0;
    const int na = act ? NAs[t] : 0;

    float acc[COB];
    #pragma unroll
    for (int co = 0; co < COB; co++) acc[co] = 0.f;

    for (int ci0 = 0; ci0 < CIN; ci0 += CHUNK) {
        __syncthreads();
        for (int i = threadIdx.x; i < CHUNK * 27 * COB; i += 128) {
            int cil = i / (27 * COB);
            int rem = i - cil * (27 * COB);
            int tap = rem / COB;
            int co  = rem - tap * COB;
            wsh[(cil * 27 + tap) * WPAD + co] =
                wgl[((size_t)(co0 + co) * CIN + (ci0 + cil)) * 27 + tap];
        }
        __syncthreads();

        if constexpr (CIN == 1) {
            for (int k = 0; k < na; k++) {
                int p = __ldg(TAP + (size_t)k * cap + t);
                float xs = __ldg(in + (p & 0xFFFFFF));
                const float* wr = &wsh[(p >> 24) * WPAD];
                #pragma unroll
                for (int co = 0; co < COB; co++) acc[co] += xs * wr[co];
            }
        } else {
            for (int k = 0; k < na; k++) {
                int p = __ldg(TAP + (size_t)k * cap + t);
                int off = p & 0xFFFFFF;
                int tap = p >> 24;
                const float* xin = in + (size_t)off * istr + ci0;
                #pragma unroll
                for (int cq = 0; cq < CHUNK / 4; cq++) {
                    float4 xv = *reinterpret_cast<const float4*>(xin + cq * 4);
                    #pragma unroll
                    for (int j = 0; j < 4; j++) {
                        float xsv = (j == 0) ? xv.x : (j == 1) ? xv.y : (j == 2) ? xv.z : xv.w;
                        const float* wr = &wsh[((cq * 4 + j) * 27 + tap) * WPAD];
                        #pragma unroll
                        for (int co = 0; co < COB; co++) acc[co] += xsv * wr[co];
                    }
                }
            }
        }
    }

    if (act) {
        if constexpr (OUTP) {
            #pragma unroll
            for (int co = 0; co < COB; co++) {
                float r = acc[co];
                if (RELU) r = fmaxf(r, 0.f);
                out[(size_t)(co0 + co) * ostr + v] = r;
            }
        } else {
            float* op = out + (size_t)v * ostr + co0;
            #pragma unroll
            for (int co = 0; co < COB; co += 4) {
                float4 r = make_float4(acc[co], acc[co+1], acc[co+2], acc[co+3]);
                if (RELU) { r.x = fmaxf(r.x, 0.f); r.y = fmaxf(r.y, 0.f);
                            r.z = fmaxf(r.z, 0.f); r.w = fmaxf(r.w, 0.f); }
                *reinterpret_cast<float4*>(op + co) = r;
            }
        }
    }
}

// ---------------------------------------------------------------------------
// Stride-2 k=2 downsample / k=2 s=2 transpose upsample (channel-major).
// ---------------------------------------------------------------------------
template<int CIN, int COB>
__launch_bounds__(128)
__global__ void down2cm(const float* __restrict__ in, int istr,
                        const float* __restrict__ wgl,
                        const float* __restrict__ maskf,
                        const int* __restrict__ list, const int* __restrict__ cntp,
                        float* __restrict__ out, int ostr, int gout)
{
    constexpr int WPAD = COB + 1;
    __shared__ float wsh[CIN * 8 * WPAD];
    const int cnt = *cntp;
    if (blockIdx.x * 128 >= cnt) return;
    const int co0 = blockIdx.y * COB;
    for (int i = threadIdx.x; i < CIN * 8 * COB; i += 128) {
        int ci  = i / (8 * COB);
        int rem = i - ci * (8 * COB);
        int tap = rem / COB;
        int co  = rem - tap * COB;
        wsh[(ci * 8 + tap) * WPAD + co] = wgl[((size_t)(co0 + co) * CIN + ci) * 8 + tap];
    }
    __syncthreads();

    const int t = blockIdx.x * 128 + threadIdx.x;
    const bool act = t < cnt;
    const int v = act ? list[t] : 0;
    const int z = v / (gout * gout), y = (v / gout) % gout, x = v % gout;
    const int gin = gout * 2;

    float acc[COB];
    #pragma unroll
    for (int co = 0; co < COB; co++) acc[co] = 0.f;

    #pragma unroll
    for (int tap = 0; tap < 8; tap++) {
        int kd = tap >> 2, kh = (tap >> 1) & 1, kw = tap & 1;
        int off = ((2*z + kd) * gin + (2*y + kh)) * gin + (2*x + kw);
        if (act && __ldg(maskf + off) != 0.f) {
            const float* xin = in + (size_t)off * istr;
            #pragma unroll
            for (int cq = 0; cq < CIN / 4; cq++) {
                float4 xv = *reinterpret_cast<const float4*>(xin + cq * 4);
                #pragma unroll
                for (int j = 0; j < 4; j++) {
                    float xs = (j == 0) ? xv.x : (j == 1) ? xv.y : (j == 2) ? xv.z : xv.w;
                    const float* wr = &wsh[((cq * 4 + j) * 8 + tap) * WPAD];
                    #pragma unroll
                    for (int co = 0; co < COB; co++) acc[co] += xs * wr[co];
                }
            }
        }
    }

    if (act) {
        float* op = out + (size_t)v * ostr + co0;
        #pragma unroll
        for (int co = 0; co < COB; co += 4)
            *reinterpret_cast<float4*>(op + co) =
                make_float4(acc[co], acc[co+1], acc[co+2], acc[co+3]);
    }
}

template<int CIN, int COB>
__launch_bounds__(128)
__global__ void up2cm(const float* __restrict__ in, int istr,
                      const float* __restrict__ wgl,
                      const int* __restrict__ list, const int* __restrict__ cntp,
                      float* __restrict__ out, int ostr, int gout)
{
    constexpr int WPAD = COB + 1;
    __shared__ float wsh[CIN * 8 * WPAD];
    const int cnt = *cntp;
    if (blockIdx.x * 128 >= cnt) return;
    const int co0 = blockIdx.y * COB;
    for (int i = threadIdx.x; i < CIN * 8 * COB; i += 128) {
        int ci  = i / (8 * COB);
        int rem = i - ci * (8 * COB);
        int tap = rem / COB;
        int co  = rem - tap * COB;
        wsh[(ci * 8 + tap) * WPAD + co] = wgl[((size_t)(co0 + co) * CIN + ci) * 8 + tap];
    }
    __syncthreads();

    const int t = blockIdx.x * 128 + threadIdx.x;
    const bool act = t < cnt;
    const int v = act ? list[t] : 0;
    const int z = v / (gout * gout), y = (v / gout) % gout, x = v % gout;
    const int gin = gout >> 1;
    const int p   = ((z >> 1) * gin + (y >> 1)) * gin + (x >> 1);
    const int tap = (1 - (z & 1)) * 4 + (1 - (y & 1)) * 2 + (1 - (x & 1));

    float acc[COB];
    #pragma unroll
    for (int co = 0; co < COB; co++) acc[co] = 0.f;

    if (act) {
        const float* xin = in + (size_t)p * istr;
        #pragma unroll
        for (int cq = 0; cq < CIN / 4; cq++) {
            float4 xv = *reinterpret_cast<const float4*>(xin + cq * 4);
            #pragma unroll
            for (int j = 0; j < 4; j++) {
                float xs = (j == 0) ? xv.x : (j == 1) ? xv.y : (j == 2) ? xv.z : xv.w;
                const float* wr = &wsh[((cq * 4 + j) * 8 + tap) * WPAD];
                #pragma unroll
                for (int co = 0; co < COB; co++) acc[co] += xs * wr[co];
            }
        }
        float* op = out + (size_t)v * ostr + co0;
        #pragma unroll
        for (int co = 0; co < COB; co += 4)
            *reinterpret_cast<float4*>(op + co) =
                make_float4(acc[co], acc[co+1], acc[co+2], acc[co+3]);
    }
}

// ---------------------------------------------------------------------------
extern "C" void kernel_launch(void* const* d_in, const int* in_sizes, int n_in,
                              void* d_out, int out_size)
{
    const float* x     = (const float*)d_in[0];
    const float* occ   = (const float*)d_in[1];
    const float* w_in  = (const float*)d_in[2];
    const float* w_e0d = (const float*)d_in[3];
    const float* w_e0a = (const float*)d_in[4];
    const float* w_e0b = (const float*)d_in[5];
    const float* w_e1d = (const float*)d_in[6];
    const float* w_e1a = (const float*)d_in[7];
    const float* w_e1b = (const float*)d_in[8];
    const float* w_d0u = (const float*)d_in[9];
    const float* w_d0a = (const float*)d_in[10];
    const float* w_d0b = (const float*)d_in[11];
    const float* w_d1u = (const float*)d_in[12];
    const float* w_d1a = (const float*)d_in[13];
    const float* w_d1b = (const float*)d_in[14];
    const float* w_oa  = (const float*)d_in[15];
    const float* w_ob  = (const float*)d_in[16];

    float *XM, *CAT0, *A32, *A16a, *A16b, *B32a, *B32b, *CAT1, *B64;
    float *C64a, *C64b, *C64c, *M1, *M2, *WT;
    int *LIST0, *LIST1, *LIST2, *NA0, *TAP0;
    int *ENT0, *ENT1, *ENT2, *SEG0, *SEG1, *SEG2, *SGW0, *SGW1, *SGW2, *SEGC;
    int *CNT, *BCNT, *BOFF;
    cudaGetSymbolAddress((void**)&XM,   g_XM);
    cudaGetSymbolAddress((void**)&CAT0, g_CAT0);
    cudaGetSymbolAddress((void**)&A32,  g_A32);
    cudaGetSymbolAddress((void**)&A16a, g_A16a);
    cudaGetSymbolAddress((void**)&A16b, g_A16b);
    cudaGetSymbolAddress((void**)&B32a, g_B32a);
    cudaGetSymbolAddress((void**)&B32b, g_B32b);
    cudaGetSymbolAddress((void**)&CAT1, g_CAT1);
    cudaGetSymbolAddress((void**)&B64,  g_B64);
    cudaGetSymbolAddress((void**)&C64a, g_C64a);
    cudaGetSymbolAddress((void**)&C64b, g_C64b);
    cudaGetSymbolAddress((void**)&C64c, g_C64c);
    cudaGetSymbolAddress((void**)&M1,   g_M1);
    cudaGetSymbolAddress((void**)&M2,   g_M2);
    cudaGetSymbolAddress((void**)&WT,   g_WT);
    cudaGetSymbolAddress((void**)&LIST0, g_LIST0);
    cudaGetSymbolAddress((void**)&LIST1, g_LIST1);
    cudaGetSymbolAddress((void**)&LIST2, g_LIST2);
    cudaGetSymbolAddress((void**)&NA0,   g_NA0);
    cudaGetSymbolAddress((void**)&TAP0,  g_TAP0);
    cudaGetSymbolAddress((void**)&ENT0,  g_ENT0);
    cudaGetSymbolAddress((void**)&ENT1,  g_ENT1);
    cudaGetSymbolAddress((void**)&ENT2,  g_ENT2);
    cudaGetSymbolAddress((void**)&SEG0,  g_SEG0);
    cudaGetSymbolAddress((void**)&SEG1,  g_SEG1);
    cudaGetSymbolAddress((void**)&SEG2,  g_SEG2);
    cudaGetSymbolAddress((void**)&SGW0,  g_SGW0);
    cudaGetSymbolAddress((void**)&SGW1,  g_SGW1);
    cudaGetSymbolAddress((void**)&SGW2,  g_SGW2);
    cudaGetSymbolAddress((void**)&SEGC,  g_SEGC);
    cudaGetSymbolAddress((void**)&CNT,   g_CNT);
    cudaGetSymbolAddress((void**)&BCNT,  g_BCNT);
    cudaGetSymbolAddress((void**)&BOFF,  g_BOFF);

    float* OUT = (float*)d_out;

    // Masks + masked input
    k_mask_input<<<NV0/128, 128>>>(x, occ, XM, NV0);
    k_maxpool<<<NB1, 128>>>(occ, M1, G1);
    k_maxpool<<<NB2, 128>>>(M1, M2, G2);

    // Level 0: compact + per-voxel taps + 64-tile entry lists
    k_count<<<CB0, 256>>>(occ, NV0, BCNT);
    k_scan <<<1, 1024>>>(BCNT, CB0, BOFF, CNT + 0);
    k_emit <<<CB0, 256>>>(occ, NV0, BOFF, LIST0);
    k_taps<<<NB0, 128>>>(occ, LIST0, CNT + 0, G0, NV0, TAP0, NA0);
    k_zeron<<<(NVT0*27+255)/256, 256>>>(SEGC, NVT0*27);
    k_entcnt<<<NB0, 128>>>(occ, LIST0, CNT + 0, G0, SEGC);
    k_segscan<<<(NVT0+255)/256, 256>>>(SEGC, NVT0, SEG0, SGW0);
    k_entscatter<<<NB0, 128>>>(occ, LIST0, CNT + 0, G0, SGW0, ENT0);

    // Level 1
    k_count<<<CB1, 256>>>(M1, NV1, BCNT);
    k_scan <<<1, 1024>>>(BCNT, CB1, BOFF, CNT + 1);
    k_emit <<<CB1, 256>>>(M1, NV1, BOFF, LIST1);
    k_zeron<<<(NVT1*27+255)/256, 256>>>(SEGC, NVT1*27);
    k_entcnt<<<NB1, 128>>>(M1, LIST1, CNT + 1, G1, SEGC);
    k_segscan<<<(NVT1+255)/256, 256>>>(SEGC, NVT1, SEG1, SGW1);
    k_entscatter<<<NB1, 128>>>(M1, LIST1, CNT + 1, G1, SGW1, ENT1);

    // Level 2
    k_count<<<CB2, 256>>>(M2, NV2, BCNT);
    k_scan <<<1, 1024>>>(BCNT, CB2, BOFF, CNT + 2);
    k_emit <<<CB2, 256>>>(M2, NV2, BOFF, LIST2);
    k_zeron<<<(NVT2*27+255)/256, 256>>>(SEGC, NVT2*27);
    k_entcnt<<<NB2, 128>>>(M2, LIST2, CNT + 2, G2, SEGC);
    k_segscan<<<(NVT2+255)/256, 256>>>(SEGC, NVT2, SEG2, SGW2);
    k_entscatter<<<NB2, 128>>>(M2, LIST2, CNT + 2, G2, SGW2, ENT2);

    // ---- network ----
    // conv_in: 1 -> 16 (skip0 -> CAT0 ch16..31)
    conv3cm<1, 16, false, 1, false><<<dim3(NB0, 1), 128>>>(
        XM, 1, w_in, TAP0, NA0, LIST0, CNT + 0, CAT0 + 16, 32, NV0);

    // e0d: 16 -> 32
    down2cm<16, 32><<<dim3(NB1, 1), 128>>>(
        CAT0 + 16, 32, w_e0d, occ, LIST1, CNT + 1, B32a, 32, G1);
    // e0a: 32 -> 32 relu
    k_wtrans<<<(32*32*27+255)/256, 256>>>(w_e0a, 32, 32, WT);
    convg2<32, 32, true><<<dim3(NVT1, 1), 128>>>(
        B32a, 32, WT, 32, ENT1, SEG1, LIST1, CNT + 1, B32b, 32);
    // e0b: 32 -> 32 (skip1 -> CAT1 ch32..63)
    k_wtrans<<<(32*32*27+255)/256, 256>>>(w_e0b, 32, 32, WT);
    convg2<32, 32, false><<<dim3(NVT1, 1), 128>>>(
        B32b, 32, WT, 32, ENT1, SEG1, LIST1, CNT + 1, CAT1 + 32, 64);

    // e1d: 32 -> 64
    down2cm<32, 32><<<dim3(NB2, 2), 128>>>(
        CAT1 + 32, 64, w_e1d, M1, LIST2, CNT + 2, C64a, 64, G2);
    // e1a: 64 -> 64 relu
    k_wtrans<<<(64*64*27+255)/256, 256>>>(w_e1a, 64, 64, WT);
    convg2<64, 32, true><<<dim3(NVT2, 2), 128>>>(
        C64a, 64, WT, 64, ENT2, SEG2, LIST2, CNT + 2, C64b, 64);
    // e1b: 64 -> 64
    k_wtrans<<<(64*64*27+255)/256, 256>>>(w_e1b, 64, 64, WT);
    convg2<64, 32, false><<<dim3(NVT2, 2), 128>>>(
        C64b, 64, WT, 64, ENT2, SEG2, LIST2, CNT + 2, C64c, 64);

    // d0u: 64 -> 32 (into CAT1 ch0..31)
    up2cm<64, 16><<<dim3(NB1, 2), 128>>>(
        C64c, 64, w_d0u, LIST1, CNT + 1, CAT1, 64, G1);
    // d0a: 64 -> 64 relu (concat)
    k_wtrans<<<(64*64*27+255)/256, 256>>>(w_d0a, 64, 64, WT);
    convg2<64, 32, true><<<dim3(NVT1, 2), 128>>>(
        CAT1, 64, WT, 64, ENT1, SEG1, LIST1, CNT + 1, B64, 64);
    // d0b: 64 -> 32
    k_wtrans<<<(64*32*27+255)/256, 256>>>(w_d0b, 64, 32, WT);
    convg2<64, 32, false><<<dim3(NVT1, 1), 128>>>(
        B64, 64, WT, 32, ENT1, SEG1, LIST1, CNT + 1, B32a, 32);

    // d1u: 32 -> 16 (into CAT0 ch0..15)
    up2cm<32, 16><<<dim3(NB0, 1), 128>>>(
        B32a, 32, w_d1u, LIST0, CNT + 0, CAT0, 32, G0);
    // d1a: 32 -> 32 relu (concat)
    k_wtrans<<<(32*32*27+255)/256, 256>>>(w_d1a, 32, 32, WT);
    convg2<32, 32, true><<<dim3(NVT0, 1), 128>>>(
        CAT0, 32, WT, 32, ENT0, SEG0, LIST0, CNT + 0, A32, 32);
    // d1b: 32 -> 16
    k_wtrans<<<(32*16*27+255)/256, 256>>>(w_d1b, 32, 16, WT);
    convg2<32, 16, false><<<dim3(NVT0, 1), 128>>>(
        A32, 32, WT, 16, ENT0, SEG0, LIST0, CNT + 0, A16a, 16);

    // out_a: 16 -> 16 relu
    k_wtrans<<<(16*16*27+255)/256, 256>>>(w_oa, 16, 16, WT);
    convg2<16, 16, true><<<dim3(NVT0, 1), 128>>>(
        A16a, 16, WT, 16, ENT0, SEG0, LIST0, CNT + 0, A16b, 16);

    // out_b: 16 -> 5, planar output
    cudaMemsetAsync(d_out, 0, (size_t)out_size * sizeof(float));
    conv3cm<16, 5, false, 8, true><<<dim3(NB0, 1), 128>>>(
        A16b, 16, w_ob, TAP0, NA0, LIST0, CNT + 0, OUT, NV0, NV0);
}

// round 7
// speedup vs baseline: 1.0677x; 1.0677x over previous
#include <cuda_runtime.h>
#include <cstdint>

// ---------------------------------------------------------------------------
// Sparse (occupancy-masked) 3D U-Net, 96^3, NF=16.
// R6 = R4 (tap-segmented gather-GEMM, entry-per-thread) +
//   - COB=64 single-pass for CIN=64 layers (no grid.y duplication)
//   - linear coalesced weight staging (co0==0 everywhere)
//   - single fused weight-transpose kernel
// ---------------------------------------------------------------------------

#define G0 96
#define G1 48
#define G2 24
#define NV0 (G0*G0*G0)   // 884736
#define NV1 (G1*G1*G1)   // 110592
#define NV2 (G2*G2*G2)   // 13824
#define CB0 (NV0/256)
#define CB1 (NV1/256)
#define CB2 (NV2/256)
#define NB0 ((NV0+127)/128)  // 6912
#define NB1 ((NV1+127)/128)  // 864
#define NB2 ((NV2+127)/128)  // 108
#define ENTCAP 3456          // 128*27 entries per block

// Activations, channel-major [voxel][channel]
__device__ float g_XM  [NV0];
__device__ float g_CAT0[(size_t)32*NV0];
__device__ float g_A32 [(size_t)32*NV0];
__device__ float g_A16a[(size_t)16*NV0];
__device__ float g_A16b[(size_t)16*NV0];
__device__ float g_B32a[(size_t)32*NV1];
__device__ float g_B32b[(size_t)32*NV1];
__device__ float g_CAT1[(size_t)64*NV1];
__device__ float g_B64 [(size_t)64*NV1];
__device__ float g_C64a[(size_t)64*NV2];
__device__ float g_C64b[(size_t)64*NV2];
__device__ float g_C64c[(size_t)64*NV2];
__device__ float g_M1[NV1];
__device__ float g_M2[NV2];

// Transposed-weight arena [tap][ci][co] per layer, at fixed offsets
#define WOFF_E0A 0
#define WOFF_E0B 27648
#define WOFF_E1A 55296
#define WOFF_E1B 165888
#define WOFF_D0A 276480
#define WOFF_D0B 387072
#define WOFF_D1A 442368
#define WOFF_D1B 470016
#define WOFF_OA  483840
#define WTOT     490752
__device__ float g_WT[WTOT];

__device__ int g_LIST0[NV0], g_LIST1[NV1], g_LIST2[NV2];
__device__ int g_NA0[NV0];
__device__ int g_TAP0[(size_t)27*NV0];
__device__ int g_ENT0[(size_t)NB0*ENTCAP];
__device__ int g_ENT1[(size_t)NB1*ENTCAP];
__device__ int g_ENT2[(size_t)NB2*ENTCAP];
__device__ int g_SEG0[NB0*28], g_SEG1[NB1*28], g_SEG2[NB2*28];
__device__ int g_SGW0[NB0*27], g_SGW1[NB1*27], g_SGW2[NB2*27];
__device__ int g_SEGC[NB0*27];
__device__ int g_CNT[4];
__device__ int g_BCNT[CB0], g_BOFF[CB0];

// ---------------------------------------------------------------------------
__global__ void k_mask_input(const float* __restrict__ x,
                             const float* __restrict__ occ,
                             float* __restrict__ xm, int n)
{
    int v = blockIdx.x * blockDim.x + threadIdx.x;
    if (v < n) xm[v] = x[v] * occ[v];
}

__global__ void k_maxpool(const float* __restrict__ in,
                          float* __restrict__ out, int gout)
{
    int v = blockIdx.x * blockDim.x + threadIdx.x;
    int n = gout * gout * gout;
    if (v >= n) return;
    int gin = gout * 2;
    int z = v / (gout * gout), y = (v / gout) % gout, x = v % gout;
    float mx = 0.f;
    #pragma unroll
    for (int a = 0; a < 2; a++)
        #pragma unroll
        for (int b = 0; b < 2; b++)
            #pragma unroll
            for (int c = 0; c < 2; c++)
                mx = fmaxf(mx, in[((size_t)(2*z+a)*gin + (2*y+b))*gin + (2*x+c)]);
    out[v] = mx;
}

// --- deterministic compaction ---------------------------------------------
__global__ void k_count(const float* __restrict__ m, int n, int* __restrict__ bcnt)
{
    int v = blockIdx.x * 256 + threadIdx.x;
    bool a = (v < n) && (m[v] != 0.f);
    unsigned bal = __ballot_sync(0xffffffffu, a);
    __shared__ int wc[8];
    if ((threadIdx.x & 31) == 0) wc[threadIdx.x >> 5] = __popc(bal);
    __syncthreads();
    if (threadIdx.x == 0) {
        int s = 0;
        #pragma unroll
        for (int i = 0; i < 8; i++) s += wc[i];
        bcnt[blockIdx.x] = s;
    }
}

__global__ void k_scan(const int* __restrict__ bcnt, int nb,
                       int* __restrict__ boff, int* __restrict__ total)
{
    __shared__ int sh[1024];
    __shared__ int carry;
    if (threadIdx.x == 0) carry = 0;
    __syncthreads();
    for (int base = 0; base < nb; base += 1024) {
        int i = base + threadIdx.x;
        int v = (i < nb) ? bcnt[i] : 0;
        sh[threadIdx.x] = v;
        __syncthreads();
        for (int d = 1; d < 1024; d <<= 1) {
            int t = (threadIdx.x >= d) ? sh[threadIdx.x - d] : 0;
            __syncthreads();
            sh[threadIdx.x] += t;
            __syncthreads();
        }
        if (i < nb) boff[i] = carry + sh[threadIdx.x] - v;
        __syncthreads();
        if (threadIdx.x == 0) carry += sh[1023];
        __syncthreads();
    }
    if (threadIdx.x == 0) *total = carry;
}

__global__ void k_emit(const float* __restrict__ m, int n,
                       const int* __restrict__ boff, int* __restrict__ list)
{
    int v = blockIdx.x * 256 + threadIdx.x;
    bool a = (v < n) && (m[v] != 0.f);
    unsigned bal = __ballot_sync(0xffffffffu, a);
    __shared__ int wc[8];
    if ((threadIdx.x & 31) == 0) wc[threadIdx.x >> 5] = __popc(bal);
    __syncthreads();
    int wid = threadIdx.x >> 5;
    int off = boff[blockIdx.x];
    for (int i = 0; i < wid; i++) off += wc[i];
    off += __popc(bal & ((1u << (threadIdx.x & 31)) - 1u));
    if (a) list[off] = v;
}

// --- per-voxel tap lists (for CIN==1 conv_in and planar out_b) ------------
__global__ void k_taps(const float* __restrict__ m, const int* __restrict__ list,
                       const int* __restrict__ cntp, int g, int cap,
                       int* __restrict__ TAP, int* __restrict__ NA)
{
    int cnt = *cntp;
    int t = blockIdx.x * 128 + threadIdx.x;
    if (t >= cnt) return;
    int v = list[t];
    int gg = g * g;
    int z = v / gg, y = (v / g) % g, x = v % g;
    int na = 0;
    #pragma unroll
    for (int dz = -1; dz <= 1; dz++) {
        int zz = z + dz; if ((unsigned)zz >= (unsigned)g) continue;
        #pragma unroll
        for (int dy = -1; dy <= 1; dy++) {
            int yy = y + dy; if ((unsigned)yy >= (unsigned)g) continue;
            int ro = (zz * g + yy) * g;
            #pragma unroll
            for (int dx = -1; dx <= 1; dx++) {
                int xx = x + dx; if ((unsigned)xx >= (unsigned)g) continue;
                int o = ro + xx;
                if (__ldg(m + o) != 0.f) {
                    int tap = (dz + 1) * 9 + (dy + 1) * 3 + (dx + 1);
                    TAP[(size_t)na * cap + t] = (tap << 24) | o;
                    na++;
                }
            }
        }
    }
    NA[t] = na;
}

// --- per-(block,tap) entry lists ------------------------------------------
__global__ void k_zeron(int* __restrict__ a, int n)
{
    int i = blockIdx.x * 256 + threadIdx.x;
    if (i < n) a[i] = 0;
}

__global__ void k_entcnt(const float* __restrict__ m, const int* __restrict__ list,
                         const int* __restrict__ cntp, int g, int* __restrict__ segc)
{
    int cnt = *cntp;
    int t = blockIdx.x * 128 + threadIdx.x;
    if (t >= cnt) return;
    int v = list[t];
    int b = t >> 7;
    int gg = g * g;
    int z = v / gg, y = (v / g) % g, x = v % g;
    #pragma unroll
    for (int dz = -1; dz <= 1; dz++) {
        int zz = z + dz; if ((unsigned)zz >= (unsigned)g) continue;
        #pragma unroll
        for (int dy = -1; dy <= 1; dy++) {
            int yy = y + dy; if ((unsigned)yy >= (unsigned)g) continue;
            int ro = (zz * g + yy) * g;
            #pragma unroll
            for (int dx = -1; dx <= 1; dx++) {
                int xx = x + dx; if ((unsigned)xx >= (unsigned)g) continue;
                if (__ldg(m + ro + xx) != 0.f) {
                    int tap = (dz + 1) * 9 + (dy + 1) * 3 + (dx + 1);
                    atomicAdd(&segc[b * 27 + tap], 1);
                }
            }
        }
    }
}

__global__ void k_segscan(const int* __restrict__ segc, int nb,
                          int* __restrict__ seg, int* __restrict__ segw)
{
    int b = blockIdx.x * 256 + threadIdx.x;
    if (b >= nb) return;
    int s = 0;
    #pragma unroll
    for (int t = 0; t < 27; t++) {
        seg[b * 28 + t] = s;
        segw[b * 27 + t] = s;
        s += segc[b * 27 + t];
    }
    seg[b * 28 + 27] = s;
}

__global__ void k_entscatter(const float* __restrict__ m, const int* __restrict__ list,
                             const int* __restrict__ cntp, int g,
                             int* __restrict__ segw, int* __restrict__ ENT)
{
    int cnt = *cntp;
    int t = blockIdx.x * 128 + threadIdx.x;
    if (t >= cnt) return;
    int v = list[t];
    int b = t >> 7;
    int slot = t & 127;
    int gg = g * g;
    int z = v / gg, y = (v / g) % g, x = v % g;
    #pragma unroll
    for (int dz = -1; dz <= 1; dz++) {
        int zz = z + dz; if ((unsigned)zz >= (unsigned)g) continue;
        #pragma unroll
        for (int dy = -1; dy <= 1; dy++) {
            int yy = y + dy; if ((unsigned)yy >= (unsigned)g) continue;
            int ro = (zz * g + yy) * g;
            #pragma unroll
            for (int dx = -1; dx <= 1; dx++) {
                int xx = x + dx; if ((unsigned)xx >= (unsigned)g) continue;
                int o = ro + xx;
                if (__ldg(m + o) != 0.f) {
                    int tap = (dz + 1) * 9 + (dy + 1) * 3 + (dx + 1);
                    int pos = atomicAdd(&segw[b * 27 + tap], 1);
                    ENT[(size_t)b * ENTCAP + pos] = (slot << 24) | o;
                }
            }
        }
    }
}

// --- fused weight transpose: all 9 conv3 layers, OIDHW -> [tap][ci][co] ----
__global__ void k_wtrans_all(const float* __restrict__ s0, const float* __restrict__ s1,
                             const float* __restrict__ s2, const float* __restrict__ s3,
                             const float* __restrict__ s4, const float* __restrict__ s5,
                             const float* __restrict__ s6, const float* __restrict__ s7,
                             const float* __restrict__ s8, float* __restrict__ wt)
{
    const int cin_[9]  = {32, 32, 64, 64, 64, 64, 32, 32, 16};
    const int cout_[9] = {32, 32, 64, 64, 64, 32, 32, 16, 16};
    const int off_[9]  = {WOFF_E0A, WOFF_E0B, WOFF_E1A, WOFF_E1B, WOFF_D0A,
                          WOFF_D0B, WOFF_D1A, WOFF_D1B, WOFF_OA};
    const float* src_[9] = {s0, s1, s2, s3, s4, s5, s6, s7, s8};
    int seg = blockIdx.y;
    int cin = cin_[seg], cout = cout_[seg];
    int tot = cin * cout * 27;
    int i = blockIdx.x * 256 + threadIdx.x;
    if (i >= tot) return;
    int co = i % cout;
    int r = i / cout;
    int ci = r % cin;
    int tap = r / cin;
    wt[off_[seg] + i] = src_[seg][((size_t)co * cin + ci) * 27 + tap];
}

// ---------------------------------------------------------------------------
// Tap-segmented gather-GEMM conv (entry-per-thread). Single co pass (co0==0).
// Weight staging = linear coalesced copy of [tap][ci][co]. Dynamic smem.
// Deterministic: ascending taps, one entry per (voxel, tap).
// ---------------------------------------------------------------------------
template<int CIN, int COB, bool RELU>
__launch_bounds__(128)
__global__ void convgemm(const float* __restrict__ in, int istr,
                         const float* __restrict__ wt,
                         const int* __restrict__ ENT, const int* __restrict__ SEG,
                         const int* __restrict__ list, const int* __restrict__ cntp,
                         float* __restrict__ out, int ostr)
{
    constexpr int ASTR = COB + 1;   // odd stride: conflict-free slot RMW
    extern __shared__ float smem[];
    float* acc = smem;              // 128 * ASTR
    float* wsh = smem + 128 * ASTR; // CIN * COB
    const int cnt = *cntp;
    const int b = blockIdx.x;
    if (b * 128 >= cnt) return;
    const int tid = threadIdx.x;

    for (int i = tid; i < 128 * ASTR; i += 128) acc[i] = 0.f;

    for (int tap = 0; tap < 27; tap++) {
        __syncthreads();
        #pragma unroll 4
        for (int i = tid; i < CIN * COB; i += 128)
            wsh[i] = __ldg(wt + tap * CIN * COB + i);
        __syncthreads();
        const int s = SEG[b * 28 + tap];
        const int n = SEG[b * 28 + tap + 1] - s;
        if (tid < n) {
            int ent = ENT[(size_t)b * ENTCAP + s + tid];
            int slot = ent >> 24;
            int vin  = ent & 0xFFFFFF;
            const float* xr = in + (size_t)vin * istr;
            float a[COB];
            #pragma unroll
            for (int co = 0; co < COB; co++) a[co] = 0.f;
            #pragma unroll 1
            for (int ci0 = 0; ci0 < CIN; ci0 += 8) {
                float4 x0 = *reinterpret_cast<const float4*>(xr + ci0);
                float4 x1 = *reinterpret_cast<const float4*>(xr + ci0 + 4);
                float xs[8] = {x0.x, x0.y, x0.z, x0.w, x1.x, x1.y, x1.z, x1.w};
                #pragma unroll
                for (int j = 0; j < 8; j++) {
                    const float* wr = &wsh[(ci0 + j) * COB];
                    #pragma unroll
                    for (int co4 = 0; co4 < COB; co4 += 4) {
                        float4 w = *reinterpret_cast<const float4*>(wr + co4);
                        a[co4+0] += xs[j] * w.x;
                        a[co4+1] += xs[j] * w.y;
                        a[co4+2] += xs[j] * w.z;
                        a[co4+3] += xs[j] * w.w;
                    }
                }
            }
            float* ap = &acc[slot * ASTR];
            #pragma unroll
            for (int co = 0; co < COB; co++) ap[co] += a[co];
        }
    }
    __syncthreads();
    const int t = b * 128 + tid;
    if (t < cnt) {
        int v = list[t];
        float* op = out + (size_t)v * ostr;
        const float* ap = &acc[tid * ASTR];
        #pragma unroll
        for (int co = 0; co < COB; co += 4) {
            float4 r = make_float4(ap[co], ap[co+1], ap[co+2], ap[co+3]);
            if (RELU) { r.x = fmaxf(r.x, 0.f); r.y = fmaxf(r.y, 0.f);
                        r.z = fmaxf(r.z, 0.f); r.w = fmaxf(r.w, 0.f); }
            *reinterpret_cast<float4*>(op + co) = r;
        }
    }
}

// ---------------------------------------------------------------------------
// R3-style conv kept for CIN==1 (conv_in) and planar-out (out_b) layers.
// ---------------------------------------------------------------------------
template<int CIN, int COB, bool RELU, int CHUNK, bool OUTP>
__launch_bounds__(128)
__global__ void conv3cm(const float* __restrict__ in, int istr,
                        const float* __restrict__ wgl,
                        const int* __restrict__ TAP, const int* __restrict__ NAs,
                        const int* __restrict__ list, const int* __restrict__ cntp,
                        float* __restrict__ out, int ostr, int cap)
{
    constexpr int WPAD = COB + 1;
    __shared__ float wsh[CHUNK * 27 * WPAD];
    const int cnt = *cntp;
    if (blockIdx.x * 128 >= cnt) return;
    const int co0 = blockIdx.y * COB;
    const int t   = blockIdx.x * 128 + threadIdx.x;
    const bool act = t < cnt;
    const int v  = act ? list[t] : 0;
    const int na = act ? NAs[t] : 0;

    float acc[COB];
    #pragma unroll
    for (int co = 0; co < COB; co++) acc[co] = 0.f;

    for (int ci0 = 0; ci0 < CIN; ci0 += CHUNK) {
        __syncthreads();
        for (int i = threadIdx.x; i < CHUNK * 27 * COB; i += 128) {
            int cil = i / (27 * COB);
            int rem = i - cil * (27 * COB);
            int tap = rem / COB;
            int co  = rem - tap * COB;
            wsh[(cil * 27 + tap) * WPAD + co] =
                wgl[((size_t)(co0 + co) * CIN + (ci0 + cil)) * 27 + tap];
        }
        __syncthreads();

        if constexpr (CIN == 1) {
            for (int k = 0; k < na; k++) {
                int p = __ldg(TAP + (size_t)k * cap + t);
                float xs = __ldg(in + (p & 0xFFFFFF));
                const float* wr = &wsh[(p >> 24) * WPAD];
                #pragma unroll
                for (int co = 0; co < COB; co++) acc[co] += xs * wr[co];
            }
        } else {
            for (int k = 0; k < na; k++) {
                int p = __ldg(TAP + (size_t)k * cap + t);
                int off = p & 0xFFFFFF;
                int tap = p >> 24;
                const float* xin = in + (size_t)off * istr + ci0;
                #pragma unroll
                for (int cq = 0; cq < CHUNK / 4; cq++) {
                    float4 xv = *reinterpret_cast<const float4*>(xin + cq * 4);
                    #pragma unroll
                    for (int j = 0; j < 4; j++) {
                        float xsv = (j == 0) ? xv.x : (j == 1) ? xv.y : (j == 2) ? xv.z : xv.w;
                        const float* wr = &wsh[((cq * 4 + j) * 27 + tap) * WPAD];
                        #pragma unroll
                        for (int co = 0; co < COB; co++) acc[co] += xsv * wr[co];
                    }
                }
            }
        }
    }

    if (act) {
        if constexpr (OUTP) {
            #pragma unroll
            for (int co = 0; co < COB; co++) {
                float r = acc[co];
                if (RELU) r = fmaxf(r, 0.f);
                out[(size_t)(co0 + co) * ostr + v] = r;
            }
        } else {
            float* op = out + (size_t)v * ostr + co0;
            #pragma unroll
            for (int co = 0; co < COB; co += 4) {
                float4 r = make_float4(acc[co], acc[co+1], acc[co+2], acc[co+3]);
                if (RELU) { r.x = fmaxf(r.x, 0.f); r.y = fmaxf(r.y, 0.f);
                            r.z = fmaxf(r.z, 0.f); r.w = fmaxf(r.w, 0.f); }
                *reinterpret_cast<float4*>(op + co) = r;
            }
        }
    }
}

// ---------------------------------------------------------------------------
// Stride-2 k=2 downsample / k=2 s=2 transpose upsample (channel-major).
// ---------------------------------------------------------------------------
template<int CIN, int COB>
__launch_bounds__(128)
__global__ void down2cm(const float* __restrict__ in, int istr,
                        const float* __restrict__ wgl,
                        const float* __restrict__ maskf,
                        const int* __restrict__ list, const int* __restrict__ cntp,
                        float* __restrict__ out, int ostr, int gout)
{
    constexpr int WPAD = COB + 1;
    __shared__ float wsh[CIN * 8 * WPAD];
    const int cnt = *cntp;
    if (blockIdx.x * 128 >= cnt) return;
    const int co0 = blockIdx.y * COB;
    for (int i = threadIdx.x; i < CIN * 8 * COB; i += 128) {
        int ci  = i / (8 * COB);
        int rem = i - ci * (8 * COB);
        int tap = rem / COB;
        int co  = rem - tap * COB;
        wsh[(ci * 8 + tap) * WPAD + co] = wgl[((size_t)(co0 + co) * CIN + ci) * 8 + tap];
    }
    __syncthreads();

    const int t = blockIdx.x * 128 + threadIdx.x;
    const bool act = t < cnt;
    const int v = act ? list[t] : 0;
    const int z = v / (gout * gout), y = (v / gout) % gout, x = v % gout;
    const int gin = gout * 2;

    float acc[COB];
    #pragma unroll
    for (int co = 0; co < COB; co++) acc[co] = 0.f;

    #pragma unroll
    for (int tap = 0; tap < 8; tap++) {
        int kd = tap >> 2, kh = (tap >> 1) & 1, kw = tap & 1;
        int off = ((2*z + kd) * gin + (2*y + kh)) * gin + (2*x + kw);
        if (act && __ldg(maskf + off) != 0.f) {
            const float* xin = in + (size_t)off * istr;
            #pragma unroll
            for (int cq = 0; cq < CIN / 4; cq++) {
                float4 xv = *reinterpret_cast<const float4*>(xin + cq * 4);
                #pragma unroll
                for (int j = 0; j < 4; j++) {
                    float xs = (j == 0) ? xv.x : (j == 1) ? xv.y : (j == 2) ? xv.z : xv.w;
                    const float* wr = &wsh[((cq * 4 + j) * 8 + tap) * WPAD];
                    #pragma unroll
                    for (int co = 0; co < COB; co++) acc[co] += xs * wr[co];
                }
            }
        }
    }

    if (act) {
        float* op = out + (size_t)v * ostr + co0;
        #pragma unroll
        for (int co = 0; co < COB; co += 4)
            *reinterpret_cast<float4*>(op + co) =
                make_float4(acc[co], acc[co+1], acc[co+2], acc[co+3]);
    }
}

template<int CIN, int COB>
__launch_bounds__(128)
__global__ void up2cm(const float* __restrict__ in, int istr,
                      const float* __restrict__ wgl,
                      const int* __restrict__ list, const int* __restrict__ cntp,
                      float* __restrict__ out, int ostr, int gout)
{
    constexpr int WPAD = COB + 1;
    __shared__ float wsh[CIN * 8 * WPAD];
    const int cnt = *cntp;
    if (blockIdx.x * 128 >= cnt) return;
    const int co0 = blockIdx.y * COB;
    for (int i = threadIdx.x; i < CIN * 8 * COB; i += 128) {
        int ci  = i / (8 * COB);
        int rem = i - ci * (8 * COB);
        int tap = rem / COB;
        int co  = rem - tap * COB;
        wsh[(ci * 8 + tap) * WPAD + co] = wgl[((size_t)(co0 + co) * CIN + ci) * 8 + tap];
    }
    __syncthreads();

    const int t = blockIdx.x * 128 + threadIdx.x;
    const bool act = t < cnt;
    const int v = act ? list[t] : 0;
    const int z = v / (gout * gout), y = (v / gout) % gout, x = v % gout;
    const int gin = gout >> 1;
    const int p   = ((z >> 1) * gin + (y >> 1)) * gin + (x >> 1);
    const int tap = (1 - (z & 1)) * 4 + (1 - (y & 1)) * 2 + (1 - (x & 1));

    float acc[COB];
    #pragma unroll
    for (int co = 0; co < COB; co++) acc[co] = 0.f;

    if (act) {
        const float* xin = in + (size_t)p * istr;
        #pragma unroll
        for (int cq = 0; cq < CIN / 4; cq++) {
            float4 xv = *reinterpret_cast<const float4*>(xin + cq * 4);
            #pragma unroll
            for (int j = 0; j < 4; j++) {
                float xs = (j == 0) ? xv.x : (j == 1) ? xv.y : (j == 2) ? xv.z : xv.w;
                const float* wr = &wsh[((cq * 4 + j) * 8 + tap) * WPAD];
                #pragma unroll
                for (int co = 0; co < COB; co++) acc[co] += xs * wr[co];
            }
        }
        float* op = out + (size_t)v * ostr + co0;
        #pragma unroll
        for (int co = 0; co < COB; co += 4)
            *reinterpret_cast<float4*>(op + co) =
                make_float4(acc[co], acc[co+1], acc[co+2], acc[co+3]);
    }
}

// ---------------------------------------------------------------------------
extern "C" void kernel_launch(void* const* d_in, const int* in_sizes, int n_in,
                              void* d_out, int out_size)
{
    const float* x     = (const float*)d_in[0];
    const float* occ   = (const float*)d_in[1];
    const float* w_in  = (const float*)d_in[2];
    const float* w_e0d = (const float*)d_in[3];
    const float* w_e0a = (const float*)d_in[4];
    const float* w_e0b = (const float*)d_in[5];
    const float* w_e1d = (const float*)d_in[6];
    const float* w_e1a = (const float*)d_in[7];
    const float* w_e1b = (const float*)d_in[8];
    const float* w_d0u = (const float*)d_in[9];
    const float* w_d0a = (const float*)d_in[10];
    const float* w_d0b = (const float*)d_in[11];
    const float* w_d1u = (const float*)d_in[12];
    const float* w_d1a = (const float*)d_in[13];
    const float* w_d1b = (const float*)d_in[14];
    const float* w_oa  = (const float*)d_in[15];
    const float* w_ob  = (const float*)d_in[16];

    float *XM, *CAT0, *A32, *A16a, *A16b, *B32a, *B32b, *CAT1, *B64;
    float *C64a, *C64b, *C64c, *M1, *M2, *WT;
    int *LIST0, *LIST1, *LIST2, *NA0, *TAP0;
    int *ENT0, *ENT1, *ENT2, *SEG0, *SEG1, *SEG2, *SGW0, *SGW1, *SGW2, *SEGC;
    int *CNT, *BCNT, *BOFF;
    cudaGetSymbolAddress((void**)&XM,   g_XM);
    cudaGetSymbolAddress((void**)&CAT0, g_CAT0);
    cudaGetSymbolAddress((void**)&A32,  g_A32);
    cudaGetSymbolAddress((void**)&A16a, g_A16a);
    cudaGetSymbolAddress((void**)&A16b, g_A16b);
    cudaGetSymbolAddress((void**)&B32a, g_B32a);
    cudaGetSymbolAddress((void**)&B32b, g_B32b);
    cudaGetSymbolAddress((void**)&CAT1, g_CAT1);
    cudaGetSymbolAddress((void**)&B64,  g_B64);
    cudaGetSymbolAddress((void**)&C64a, g_C64a);
    cudaGetSymbolAddress((void**)&C64b, g_C64b);
    cudaGetSymbolAddress((void**)&C64c, g_C64c);
    cudaGetSymbolAddress((void**)&M1,   g_M1);
    cudaGetSymbolAddress((void**)&M2,   g_M2);
    cudaGetSymbolAddress((void**)&WT,   g_WT);
    cudaGetSymbolAddress((void**)&LIST0, g_LIST0);
    cudaGetSymbolAddress((void**)&LIST1, g_LIST1);
    cudaGetSymbolAddress((void**)&LIST2, g_LIST2);
    cudaGetSymbolAddress((void**)&NA0,   g_NA0);
    cudaGetSymbolAddress((void**)&TAP0,  g_TAP0);
    cudaGetSymbolAddress((void**)&ENT0,  g_ENT0);
    cudaGetSymbolAddress((void**)&ENT1,  g_ENT1);
    cudaGetSymbolAddress((void**)&ENT2,  g_ENT2);
    cudaGetSymbolAddress((void**)&SEG0,  g_SEG0);
    cudaGetSymbolAddress((void**)&SEG1,  g_SEG1);
    cudaGetSymbolAddress((void**)&SEG2,  g_SEG2);
    cudaGetSymbolAddress((void**)&SGW0,  g_SGW0);
    cudaGetSymbolAddress((void**)&SGW1,  g_SGW1);
    cudaGetSymbolAddress((void**)&SGW2,  g_SGW2);
    cudaGetSymbolAddress((void**)&SEGC,  g_SEGC);
    cudaGetSymbolAddress((void**)&CNT,   g_CNT);
    cudaGetSymbolAddress((void**)&BCNT,  g_BCNT);
    cudaGetSymbolAddress((void**)&BOFF,  g_BOFF);

    float* OUT = (float*)d_out;

    // Opt-in dynamic smem for the 64->64 convgemm (49.7 KB)
    cudaFuncSetAttribute(convgemm<64, 64, true>,
                         cudaFuncAttributeMaxDynamicSharedMemorySize, 50176);
    cudaFuncSetAttribute(convgemm<64, 64, false>,
                         cudaFuncAttributeMaxDynamicSharedMemorySize, 50176);

    // smem sizes (bytes): acc 128*(COB+1) + wsh CIN*COB floats
    const int SM3232 = (128 * 33 + 32 * 32) * 4;   // 20992
    const int SM6464 = (128 * 65 + 64 * 64) * 4;   // 49664
    const int SM6432 = (128 * 33 + 64 * 32) * 4;   // 25088
    const int SM3216 = (128 * 17 + 32 * 16) * 4;   // 10752
    const int SM1616 = (128 * 17 + 16 * 16) * 4;   // 9728

    // Masks + masked input
    k_mask_input<<<NV0/128, 128>>>(x, occ, XM, NV0);
    k_maxpool<<<NB1, 128>>>(occ, M1, G1);
    k_maxpool<<<NB2, 128>>>(M1, M2, G2);

    // Fused weight transpose (all 9 conv3 layers)
    k_wtrans_all<<<dim3(432, 9), 256>>>(w_e0a, w_e0b, w_e1a, w_e1b, w_d0a,
                                        w_d0b, w_d1a, w_d1b, w_oa, WT);

    // Level 0: compact + per-voxel taps + block-tap entry lists
    k_count<<<CB0, 256>>>(occ, NV0, BCNT);
    k_scan <<<1, 1024>>>(BCNT, CB0, BOFF, CNT + 0);
    k_emit <<<CB0, 256>>>(occ, NV0, BOFF, LIST0);
    k_taps<<<NB0, 128>>>(occ, LIST0, CNT + 0, G0, NV0, TAP0, NA0);
    k_zeron<<<(NB0*27+255)/256, 256>>>(SEGC, NB0*27);
    k_entcnt<<<NB0, 128>>>(occ, LIST0, CNT + 0, G0, SEGC);
    k_segscan<<<(NB0+255)/256, 256>>>(SEGC, NB0, SEG0, SGW0);
    k_entscatter<<<NB0, 128>>>(occ, LIST0, CNT + 0, G0, SGW0, ENT0);

    // Level 1
    k_count<<<CB1, 256>>>(M1, NV1, BCNT);
    k_scan <<<1, 1024>>>(BCNT, CB1, BOFF, CNT + 1);
    k_emit <<<CB1, 256>>>(M1, NV1, BOFF, LIST1);
    k_zeron<<<(NB1*27+255)/256, 256>>>(SEGC, NB1*27);
    k_entcnt<<<NB1, 128>>>(M1, LIST1, CNT + 1, G1, SEGC);
    k_segscan<<<(NB1+255)/256, 256>>>(SEGC, NB1, SEG1, SGW1);
    k_entscatter<<<NB1, 128>>>(M1, LIST1, CNT + 1, G1, SGW1, ENT1);

    // Level 2
    k_count<<<CB2, 256>>>(M2, NV2, BCNT);
    k_scan <<<1, 1024>>>(BCNT, CB2, BOFF, CNT + 2);
    k_emit <<<CB2, 256>>>(M2, NV2, BOFF, LIST2);
    k_zeron<<<(NB2*27+255)/256, 256>>>(SEGC, NB2*27);
    k_entcnt<<<NB2, 128>>>(M2, LIST2, CNT + 2, G2, SEGC);
    k_segscan<<<(NB2+255)/256, 256>>>(SEGC, NB2, SEG2, SGW2);
    k_entscatter<<<NB2, 128>>>(M2, LIST2, CNT + 2, G2, SGW2, ENT2);

    // ---- network ----
    // conv_in: 1 -> 16 (skip0 -> CAT0 ch16..31)
    conv3cm<1, 16, false, 1, false><<<dim3(NB0, 1), 128>>>(
        XM, 1, w_in, TAP0, NA0, LIST0, CNT + 0, CAT0 + 16, 32, NV0);

    // e0d: 16 -> 32
    down2cm<16, 32><<<dim3(NB1, 1), 128>>>(
        CAT0 + 16, 32, w_e0d, occ, LIST1, CNT + 1, B32a, 32, G1);
    // e0a: 32 -> 32 relu
    convgemm<32, 32, true><<<NB1, 128, SM3232>>>(
        B32a, 32, WT + WOFF_E0A, ENT1, SEG1, LIST1, CNT + 1, B32b, 32);
    // e0b: 32 -> 32 (skip1 -> CAT1 ch32..63)
    convgemm<32, 32, false><<<NB1, 128, SM3232>>>(
        B32b, 32, WT + WOFF_E0B, ENT1, SEG1, LIST1, CNT + 1, CAT1 + 32, 64);

    // e1d: 32 -> 64
    down2cm<32, 32><<<dim3(NB2, 2), 128>>>(
        CAT1 + 32, 64, w_e1d, M1, LIST2, CNT + 2, C64a, 64, G2);
    // e1a: 64 -> 64 relu
    convgemm<64, 64, true><<<NB2, 128, SM6464>>>(
        C64a, 64, WT + WOFF_E1A, ENT2, SEG2, LIST2, CNT + 2, C64b, 64);
    // e1b: 64 -> 64
    convgemm<64, 64, false><<<NB2, 128, SM6464>>>(
        C64b, 64, WT + WOFF_E1B, ENT2, SEG2, LIST2, CNT + 2, C64c, 64);

    // d0u: 64 -> 32 (into CAT1 ch0..31)
    up2cm<64, 16><<<dim3(NB1, 2), 128>>>(
        C64c, 64, w_d0u, LIST1, CNT + 1, CAT1, 64, G1);
    // d0a: 64 -> 64 relu (concat)
    convgemm<64, 64, true><<<NB1, 128, SM6464>>>(
        CAT1, 64, WT + WOFF_D0A, ENT1, SEG1, LIST1, CNT + 1, B64, 64);
    // d0b: 64 -> 32
    convgemm<64, 32, false><<<NB1, 128, SM6432>>>(
        B64, 64, WT + WOFF_D0B, ENT1, SEG1, LIST1, CNT + 1, B32a, 32);

    // d1u: 32 -> 16 (into CAT0 ch0..15)
    up2cm<32, 16><<<dim3(NB0, 1), 128>>>(
        B32a, 32, w_d1u, LIST0, CNT + 0, CAT0, 32, G0);
    // d1a: 32 -> 32 relu (concat)
    convgemm<32, 32, true><<<NB0, 128, SM3232>>>(
        CAT0, 32, WT + WOFF_D1A, ENT0, SEG0, LIST0, CNT + 0, A32, 32);
    // d1b: 32 -> 16
    convgemm<32, 16, false><<<NB0, 128, SM3216>>>(
        A32, 32, WT + WOFF_D1B, ENT0, SEG0, LIST0, CNT + 0, A16a, 16);

    // out_a: 16 -> 16 relu
    convgemm<16, 16, true><<<NB0, 128, SM1616>>>(
        A16a, 16, WT + WOFF_OA, ENT0, SEG0, LIST0, CNT + 0, A16b, 16);

    // out_b: 16 -> 5, planar output
    cudaMemsetAsync(d_out, 0, (size_t)out_size * sizeof(float));
    conv3cm<16, 5, false, 8, true><<<dim3(NB0, 1), 128>>>(
        A16b, 16, w_ob, TAP0, NA0, LIST0, CNT + 0, OUT, NV0, NV0);
}